// round 1
// baseline (speedup 1.0000x reference)
#include <cuda_runtime.h>
#include <cuda_bf16.h>

#define HH 64
#define WW 64
#define CC 256
#define KK 64
#define PHB 7
#define PWB 7
#define SCALE_F 0.25f

__device__ __forceinline__ float bsample(const float* __restrict__ f,
                                         const float* __restrict__ m,
                                         float y, float x) {
    // torchvision RoIAlign edge handling: zero outside [-1, L]
    if (y < -1.0f || y > (float)HH || x < -1.0f || x > (float)WW) return 0.0f;
    float yc = fminf(fmaxf(y, 0.0f), (float)(HH - 1));
    float xc = fminf(fmaxf(x, 0.0f), (float)(WW - 1));
    int yl = (int)yc;
    int xl = (int)xc;
    int yh = min(yl + 1, HH - 1);
    int xh = min(xl + 1, WW - 1);
    float ly = yc - (float)yl, lx = xc - (float)xl;
    float hy = 1.0f - ly, hx = 1.0f - lx;
    int i00 = yl * WW + xl;
    int i01 = yl * WW + xh;
    int i10 = yh * WW + xl;
    int i11 = yh * WW + xh;
    float v00 = __ldg(f + i00) * __ldg(m + i00);
    float v01 = __ldg(f + i01) * __ldg(m + i01);
    float v10 = __ldg(f + i10) * __ldg(m + i10);
    float v11 = __ldg(f + i11) * __ldg(m + i11);
    return hy * (hx * v00 + lx * v01) + ly * (hx * v10 + lx * v11);
}

// One warp handles one (box k, channel c) pair: 49 output bins across 32 lanes.
// Block = 8 warps = 8 consecutive channels of one box.
// Grid = (C/8, K) = (32, 64).
__global__ __launch_bounds__(256, 8)
void masked_roialign_kernel(const float* __restrict__ feat,
                            const float* __restrict__ boxes,
                            const float* __restrict__ mask,
                            float* __restrict__ out) {
    const int warp = threadIdx.x >> 5;
    const int lane = threadIdx.x & 31;
    const int k = blockIdx.y;
    const int c = (blockIdx.x << 3) + warp;

    const float* bx = boxes + k * 5;
    const int bi = (int)__ldg(bx + 0);
    const float x1 = __ldg(bx + 1) * SCALE_F;
    const float y1 = __ldg(bx + 2) * SCALE_F;
    const float x2 = __ldg(bx + 3) * SCALE_F;
    const float y2 = __ldg(bx + 4) * SCALE_F;

    const float roi_w = fmaxf(x2 - x1, 1.0f);
    const float roi_h = fmaxf(y2 - y1, 1.0f);
    const float bw = roi_w * (1.0f / PWB);
    const float bh = roi_h * (1.0f / PHB);

    const float* f = feat + ((size_t)bi * CC + c) * (HH * WW);
    const float* m = mask + ((size_t)k * CC + c) * (HH * WW);
    float* o = out + ((size_t)k * CC + c) * (PHB * PWB);

    #pragma unroll
    for (int pass = 0; pass < 2; pass++) {
        int bin = lane + pass * 32;
        if (bin >= PHB * PWB) break;
        int py = bin / PWB;
        int px = bin - py * PWB;

        float s = 0.0f;
        #pragma unroll
        for (int sy = 0; sy < 2; sy++) {
            float y = y1 + ((float)py + ((float)sy + 0.5f) * 0.5f) * bh;
            #pragma unroll
            for (int sx = 0; sx < 2; sx++) {
                float x = x1 + ((float)px + ((float)sx + 0.5f) * 0.5f) * bw;
                s += bsample(f, m, y, x);
            }
        }
        o[bin] = s * 0.25f;
    }
}

extern "C" void kernel_launch(void* const* d_in, const int* in_sizes, int n_in,
                              void* d_out, int out_size) {
    const float* feat  = (const float*)d_in[0];   // [2,256,64,64]
    const float* boxes = (const float*)d_in[1];   // [64,5]
    const float* mask  = (const float*)d_in[2];   // [64,256,64,64]
    float* out = (float*)d_out;                   // [64,256,7,7]

    dim3 grid(CC / 8, KK);
    dim3 block(256);
    masked_roialign_kernel<<<grid, block>>>(feat, boxes, mask, out);
}

// round 2
// speedup vs baseline: 1.1933x; 1.1933x over previous
#include <cuda_runtime.h>
#include <cuda_bf16.h>

#define HH 64
#define WW 64
#define CC 256
#define KK 64
#define PHB 7
#define PWB 7
#define SCALE_F 0.25f

// One thread per output element (k, c, py, px). 64*256*49 = 802816 = 3136 * 256.
// The 4 sub-samples (SR=2 x SR=2) expand into a 4x4 outer product of row/col taps:
//   rows  = {y0_lo, y0_hi, y1_lo, y1_hi},  cols = {x0_lo, x0_hi, x1_lo, x1_hi}
//   tap weight(a,b) = wy[a] * wx[b], with validity folded into wy/wx.
// This lets ptxas batch all 32 loads (16 feat + 16 mask) before the FMA chain.
__global__ __launch_bounds__(256, 4)
void masked_roialign_kernel(const float* __restrict__ feat,
                            const float* __restrict__ boxes,
                            const float* __restrict__ mask,
                            float* __restrict__ out) {
    const int tid = blockIdx.x * 256 + threadIdx.x;

    const int bin = tid % (PHB * PWB);
    const int kc  = tid / (PHB * PWB);
    const int c   = kc & (CC - 1);
    const int k   = kc >> 8;
    const int py  = bin / PWB;
    const int px  = bin - py * PWB;

    const float* bx = boxes + k * 5;
    const int   bi = (int)__ldg(bx + 0);
    const float x1 = __ldg(bx + 1) * SCALE_F;
    const float y1 = __ldg(bx + 2) * SCALE_F;
    const float x2 = __ldg(bx + 3) * SCALE_F;
    const float y2 = __ldg(bx + 4) * SCALE_F;

    const float bw = fmaxf(x2 - x1, 1.0f) * (1.0f / PWB);
    const float bh = fmaxf(y2 - y1, 1.0f) * (1.0f / PHB);

    int   rofs[4], cofs[4];
    float wy[4], wx[4];

    // y axis: two sub-sample rows
    #pragma unroll
    for (int s = 0; s < 2; s++) {
        float v = y1 + ((float)py + ((float)s + 0.5f) * 0.5f) * bh;
        float valid = (v >= -1.0f && v <= (float)HH) ? 1.0f : 0.0f;
        float vc = fminf(fmaxf(v, 0.0f), (float)(HH - 1));
        int lo = (int)vc;
        int hi = min(lo + 1, HH - 1);
        float fr = vc - (float)lo;
        rofs[2 * s + 0] = lo * WW;
        rofs[2 * s + 1] = hi * WW;
        wy[2 * s + 0] = (1.0f - fr) * valid;
        wy[2 * s + 1] = fr * valid;
    }
    // x axis: two sub-sample cols
    #pragma unroll
    for (int s = 0; s < 2; s++) {
        float v = x1 + ((float)px + ((float)s + 0.5f) * 0.5f) * bw;
        float valid = (v >= -1.0f && v <= (float)WW) ? 1.0f : 0.0f;
        float vc = fminf(fmaxf(v, 0.0f), (float)(WW - 1));
        int lo = (int)vc;
        int hi = min(lo + 1, WW - 1);
        float fr = vc - (float)lo;
        cofs[2 * s + 0] = lo;
        cofs[2 * s + 1] = hi;
        wx[2 * s + 0] = (1.0f - fr) * valid;
        wx[2 * s + 1] = fr * valid;
    }

    const float* f = feat + ((size_t)bi * CC + c) * (HH * WW);
    const float* m = mask + ((size_t)kc) * (HH * WW);

    // Batch all 32 loads, then fold.
    float fv[16], mv[16];
    #pragma unroll
    for (int a = 0; a < 4; a++) {
        #pragma unroll
        for (int b = 0; b < 4; b++) {
            int idx = rofs[a] + cofs[b];
            fv[a * 4 + b] = __ldg(f + idx);
            mv[a * 4 + b] = __ldcs(m + idx);   // streaming: protect feature L2 residency
        }
    }

    float acc = 0.0f;
    #pragma unroll
    for (int a = 0; a < 4; a++) {
        #pragma unroll
        for (int b = 0; b < 4; b++) {
            acc += (wy[a] * wx[b]) * (fv[a * 4 + b] * mv[a * 4 + b]);
        }
    }

    out[tid] = acc * 0.25f;
}

extern "C" void kernel_launch(void* const* d_in, const int* in_sizes, int n_in,
                              void* d_out, int out_size) {
    const float* feat  = (const float*)d_in[0];   // [2,256,64,64]
    const float* boxes = (const float*)d_in[1];   // [64,5]
    const float* mask  = (const float*)d_in[2];   // [64,256,64,64]
    float* out = (float*)d_out;                   // [64,256,7,7]

    const int total = KK * CC * PHB * PWB;        // 802816
    masked_roialign_kernel<<<total / 256, 256>>>(feat, boxes, mask, out);
}